// round 15
// baseline (speedup 1.0000x reference)
#include <cuda_runtime.h>

#define Bn 16
#define Cn 20
#define Hn 512
#define Wn 512
#define W4n (Wn / 4)
#define HWn (Hn * Wn)
#define HW4n (Hn * W4n)
#define CHWn (Cn * HWn)
#define HMASK (Hn - 1)
#define W4MASK (W4n - 1)

#define GROUPS 4
#define BPG (Bn / GROUPS)     // 4 batches per group

// Scratch (__device__ globals per allocation-free rule)
__device__ unsigned g_a1[Bn * HW4n];    // step-1 mask, 1 byte/pixel (0/1)
__device__ unsigned g_e1[Bn * HW4n];    // (world1 ch0 == 3) flag, packed
__device__ float4   g_d1[Bn * HW4n];    // world1 ch1 (density after step 1)
__device__ unsigned g_code[Bn * HW4n];  // per byte: a1[h] | a1[h+1]<<1 | a2[h]<<2 | a2[h+1]<<3

// exact 0/1-coefficient blend, BRANCHLESS: (1-a)(1-b)y + a*x + b*z
__device__ __forceinline__ float selv(bool a, bool b, float x, float y, float z) {
    float t = b ? z : y;
    t = a ? x : t;
    return (a && b) ? (x + z) : t;
}

__device__ __forceinline__ unsigned cmp3(float d, float df, float da, float dfa) {
    return (unsigned)(df >= d) & (unsigned)(da < d) & (unsigned)(dfa < d);
}

// ---------------- Kernel A: step-1 mask + step-1 ch0/ch1, 4-wide ----------------
__device__ __forceinline__ void kA_lane(
    float dm, float d, float dp, float dfm, float dfc, float dfp,
    float e0m, float e0c, float e0p,
    unsigned& a1, unsigned& e1, float& d1)
{
    a1 = (unsigned)(e0c == 3.0f) & cmp3(d, dfc, dm, dfm);
    unsigned b1 = (unsigned)(e0p == 3.0f) & cmp3(dp, dfp, d, dfc);
    float e1v = selv(a1 != 0u, b1 != 0u, e0m, e0c, e0p);
    d1        = selv(a1 != 0u, b1 != 0u, dm,  d,   dp);
    e1 = (unsigned)(e1v == 3.0f);
}

__global__ void kA(const float* __restrict__ world, int b0) {
    int idx = blockIdx.x * blockDim.x + threadIdx.x;   // local: bl<<16 | h<<7 | w4
    int w4 = idx & W4MASK;
    int h  = (idx >> 7) & HMASK;
    int b  = b0 + (idx >> 16);
    int gidx = idx + (b0 << 16);
    int hm = (h - 1) & HMASK, hp = (h + 1) & HMASK;
    int w4m = (w4 - 1) & W4MASK;

    const float4* c0 = (const float4*)(world + (long)b * CHWn);
    const float4* c1 = c0 + HW4n;

    float4 c1m = c1[hm * W4n + w4], c1c = c1[h * W4n + w4], c1p = c1[hp * W4n + w4];
    float4 c1mP = c1[hm * W4n + w4m], c1cP = c1[h * W4n + w4m], c1pP = c1[hp * W4n + w4m];
    float4 c0m = c0[hm * W4n + w4], c0c = c0[h * W4n + w4], c0p = c0[hp * W4n + w4];

    unsigned a1w = 0, e1w = 0;
    float4 d1v;
    unsigned a, e; float dd;

    kA_lane(c1m.x, c1c.x, c1p.x, c1mP.w, c1cP.w, c1pP.w, c0m.x, c0c.x, c0p.x, a, e, dd);
    a1w |= a; e1w |= e; d1v.x = dd;
    kA_lane(c1m.y, c1c.y, c1p.y, c1m.x, c1c.x, c1p.x, c0m.y, c0c.y, c0p.y, a, e, dd);
    a1w |= a << 8; e1w |= e << 8; d1v.y = dd;
    kA_lane(c1m.z, c1c.z, c1p.z, c1m.y, c1c.y, c1p.y, c0m.z, c0c.z, c0p.z, a, e, dd);
    a1w |= a << 16; e1w |= e << 16; d1v.z = dd;
    kA_lane(c1m.w, c1c.w, c1p.w, c1m.z, c1c.z, c1p.z, c0m.w, c0c.w, c0p.w, a, e, dd);
    a1w |= a << 24; e1w |= e << 24; d1v.w = dd;

    g_a1[gidx] = a1w;
    g_e1[gidx] = e1w;
    g_d1[gidx] = d1v;
}

// ---------------- Kernel B: step-2 mask + packed per-pixel control byte ----------------
__global__ void kB(int b0) {
    int idx = blockIdx.x * blockDim.x + threadIdx.x;
    int w4 = idx & W4MASK;
    int h  = (idx >> 7) & HMASK;
    int b  = b0 + (idx >> 16);
    int gidx = idx + (b0 << 16);
    int hm = (h - 1) & HMASK, hp = (h + 1) & HMASK;
    int w4p = (w4 + 1) & W4MASK;
    int base = b << 16;

    const float4* d1 = g_d1 + base;
    float4 dm = d1[hm * W4n + w4],  dc = d1[h * W4n + w4],  dp = d1[hp * W4n + w4];
    float4 dmN = d1[hm * W4n + w4p], dcN = d1[h * W4n + w4p], dpN = d1[hp * W4n + w4p];
    unsigned e1c = g_e1[gidx];
    unsigned e1p = g_e1[base + hp * W4n + w4];
    unsigned a1c = g_a1[gidx];
    unsigned a1p = g_a1[base + hp * W4n + w4];

    unsigned a2c = ((e1c)        & 1u) & cmp3(dc.x, dc.y, dm.x, dm.y);
    a2c |= (((e1c >> 8)  & 1u) & cmp3(dc.y, dc.z, dm.y, dm.z)) << 8;
    a2c |= (((e1c >> 16) & 1u) & cmp3(dc.z, dc.w, dm.z, dm.w)) << 16;
    a2c |= (((e1c >> 24) & 1u) & cmp3(dc.w, dcN.x, dm.w, dmN.x)) << 24;

    unsigned a2p = ((e1p)        & 1u) & cmp3(dp.x, dp.y, dc.x, dc.y);
    a2p |= (((e1p >> 8)  & 1u) & cmp3(dp.y, dp.z, dc.y, dc.z)) << 8;
    a2p |= (((e1p >> 16) & 1u) & cmp3(dp.z, dp.w, dc.z, dc.w)) << 16;
    a2p |= (((e1p >> 24) & 1u) & cmp3(dp.w, dpN.x, dc.w, dcN.x)) << 24;

    g_code[gidx] = a1c | (a1p << 1) | (a2c << 2) | (a2p << 3);
}

// ---------------- Kernel C: fused two-step apply ----------------
#define NCH 8
#define CHUNK (Hn / NCH)   // 64

__device__ __forceinline__ float4 w1vec(unsigned cw, float4 a, float4 b, float4 c) {
    float4 o;
    o.x = selv(cw & 0x00000001u, cw & 0x00000002u, a.x, b.x, c.x);
    o.y = selv(cw & 0x00000100u, cw & 0x00000200u, a.y, b.y, c.y);
    o.z = selv(cw & 0x00010000u, cw & 0x00020000u, a.z, b.z, c.z);
    o.w = selv(cw & 0x01000000u, cw & 0x02000000u, a.w, b.w, c.w);
    return o;
}
__device__ __forceinline__ float4 outvec(unsigned cw, float4 a, float4 b, float4 c) {
    float4 o;
    o.x = selv(cw & 0x00000004u, cw & 0x00000008u, a.x, b.x, c.x);
    o.y = selv(cw & 0x00000400u, cw & 0x00000800u, a.y, b.y, c.y);
    o.z = selv(cw & 0x00040000u, cw & 0x00080000u, a.z, b.z, c.z);
    o.w = selv(cw & 0x04000000u, cw & 0x08000000u, a.w, b.w, c.w);
    return o;
}

#define ROW1(L, C, QP)                                   \
    __stcs((QP), outvec(cc, t0, t1, t2));                \
    r0 = r1; r1 = r2; r2 = r3; r3 = r4; r4 = (L);        \
    t0 = t1; t1 = t2; t2 = w1vec((C), r2, r3, r4);       \
    cc = cp; cp = (C);

__global__ void __launch_bounds__(128, 8) kC(const float* __restrict__ world,
                                             float* __restrict__ out, int b0) {
    int w4 = threadIdx.x;                 // 0..127 — full row of float4
    int h0 = blockIdx.y * CHUNK;
    int bc = blockIdx.z;                  // 0..BPG*Cn-1
    int b = b0 + bc / Cn;
    int c = bc % Cn;

    const float4* p = (const float4*)(world + (long)b * CHWn + (long)c * HWn) + w4;
    float4*       q = (float4*)(out + (long)b * CHWn + (long)c * HWn) + w4;
    const unsigned* ck = g_code + (b << 16) + w4;

    float4 r0 = p[((h0 - 2) & HMASK) * W4n];
    float4 r1 = p[((h0 - 1) & HMASK) * W4n];
    float4 r2 = p[h0 * W4n];
    float4 r3 = p[((h0 + 1) & HMASK) * W4n];
    float4 r4 = p[((h0 + 2) & HMASK) * W4n];

    unsigned cm = ck[((h0 - 1) & HMASK) * W4n];
    unsigned cc = ck[h0 * W4n];
    unsigned cp = ck[((h0 + 1) & HMASK) * W4n];

    float4 t0 = w1vec(cm, r0, r1, r2);
    float4 t1 = w1vec(cc, r1, r2, r3);
    float4 t2 = w1vec(cp, r2, r3, r4);

    if (blockIdx.y != NCH - 1) {
        const float4*   pl = p  + (h0 + 3) * W4n;
        const unsigned* cl = ck + (h0 + 2) * W4n;
        float4*         qs = q  + h0 * W4n;
        for (int hh = 0; hh < CHUNK; hh += 4) {
            float4 L0 = pl[0 * W4n], L1 = pl[1 * W4n], L2 = pl[2 * W4n], L3 = pl[3 * W4n];
            unsigned C0 = cl[0 * W4n], C1 = cl[1 * W4n], C2 = cl[2 * W4n], C3 = cl[3 * W4n];
            ROW1(L0, C0, qs + 0 * W4n)
            ROW1(L1, C1, qs + 1 * W4n)
            ROW1(L2, C2, qs + 2 * W4n)
            ROW1(L3, C3, qs + 3 * W4n)
            pl += 4 * W4n; cl += 4 * W4n; qs += 4 * W4n;
        }
    } else {
        for (int hh = 0; hh < CHUNK; hh += 4) {
            int h = h0 + hh;
            float4 L0 = p[((h + 3) & HMASK) * W4n];
            float4 L1 = p[((h + 4) & HMASK) * W4n];
            float4 L2 = p[((h + 5) & HMASK) * W4n];
            float4 L3 = p[((h + 6) & HMASK) * W4n];
            unsigned C0 = ck[((h + 2) & HMASK) * W4n];
            unsigned C1 = ck[((h + 3) & HMASK) * W4n];
            unsigned C2 = ck[((h + 4) & HMASK) * W4n];
            unsigned C3 = ck[((h + 5) & HMASK) * W4n];
            ROW1(L0, C0, q + (h + 0) * W4n)
            ROW1(L1, C1, q + (h + 1) * W4n)
            ROW1(L2, C2, q + (h + 2) * W4n)
            ROW1(L3, C3, q + (h + 3) * W4n)
        }
    }
}

// ---------------- Stream/event context (created at static init, before any checkpoint) ----------------
struct PipeCtx {
    cudaStream_t s[GROUPS - 1];
    cudaEvent_t  evMask[GROUPS - 1];   // masks of group g done (g = 0..2)
    cudaEvent_t  evDone[GROUPS - 1];   // kC of group g done (g = 1..3)
    PipeCtx() {
        for (int i = 0; i < GROUPS - 1; i++) {
            cudaStreamCreateWithFlags(&s[i], cudaStreamNonBlocking);
            cudaEventCreateWithFlags(&evMask[i], cudaEventDisableTiming);
            cudaEventCreateWithFlags(&evDone[i], cudaEventDisableTiming);
        }
    }
};
static PipeCtx g_pipe;

extern "C" void kernel_launch(void* const* d_in, const int* in_sizes, int n_in,
                              void* d_out, int out_size) {
    const float* world = (const float*)d_in[0];   // (16,20,512,512) fp32
    float* out = (float*)d_out;

    const int maskBlocks = BPG * HW4n / 256;      // 1024
    dim3 cgrid(1, NCH, BPG * Cn);                 // (1, 8, 80)

    // group 0 on the capture (default) stream
    kA<<<maskBlocks, 256>>>(world, 0);
    kB<<<maskBlocks, 256>>>(0);
    cudaEventRecord(g_pipe.evMask[0], 0);
    kC<<<cgrid, 128>>>(world, out, 0);

    // groups 1..3, each forked so its masks start after previous group's masks
    for (int g = 1; g < GROUPS; g++) {
        cudaStream_t sg = g_pipe.s[g - 1];
        cudaStreamWaitEvent(sg, g_pipe.evMask[g - 1], 0);
        kA<<<maskBlocks, 256, 0, sg>>>(world, g * BPG);
        kB<<<maskBlocks, 256, 0, sg>>>(g * BPG);
        if (g < GROUPS - 1) cudaEventRecord(g_pipe.evMask[g], sg);
        kC<<<cgrid, 128, 0, sg>>>(world, out, g * BPG);
        cudaEventRecord(g_pipe.evDone[g - 1], sg);
    }

    // join all side streams back into the capture stream
    for (int g = 0; g < GROUPS - 1; g++)
        cudaStreamWaitEvent(0, g_pipe.evDone[g], 0);
}

// round 16
// speedup vs baseline: 1.0967x; 1.0967x over previous
#include <cuda_runtime.h>

#define Bn 16
#define Cn 20
#define Hn 512
#define Wn 512
#define W4n (Wn / 4)
#define HWn (Hn * Wn)
#define HW4n (Hn * W4n)
#define CHWn (Cn * HWn)
#define HMASK (Hn - 1)
#define W4MASK (W4n - 1)

// Scratch (__device__ globals per allocation-free rule)
__device__ unsigned g_code[Bn * HW4n];  // per byte: a1[h] | a1[h+1]<<1 | a2[h]<<2 | a2[h+1]<<3

// exact 0/1-coefficient blend, BRANCHLESS: (1-a)(1-b)y + a*x + b*z
__device__ __forceinline__ float selv(bool a, bool b, float x, float y, float z) {
    float t = b ? z : y;
    t = a ? x : t;
    return (a && b) ? (x + z) : t;
}

// (df >= d) & (da < d) & (dfa < d)
__device__ __forceinline__ unsigned cmp3(float d, float df, float da, float dfa) {
    return (unsigned)(df >= d) & (unsigned)(da < d) & (unsigned)(dfa < d);
}

// ---------------- Kernel ABs: smem-fused mask pipeline -> packed control byte ----------------
// One block = one batch b, one 8-row band [hh0, hh0+8). ri coordinate: global row = hh0-2+ri.
// smem ch1 rows ri=0..11; a1 rows ri=1..11 (global hh0-1..hh0+9).
#define RB 8
#define NRB (Hn / RB)          // 64 bands
#define S1R (RB + 4)           // 12
#define SA1R (RB + 3)          // 11

__global__ void __launch_bounds__(128) kABs(const float* __restrict__ world) {
    __shared__ float4  s1[S1R][W4n];        // ch1 band rows
    __shared__ unsigned sa1[SA1R][W4n];     // a1 bits, [ri-1][w4], 0/1 per byte lane

    int w4 = threadIdx.x;                   // 0..127
    int w4m = (w4 - 1) & W4MASK;
    int w4p = (w4 + 1) & W4MASK;
    int hh0 = blockIdx.x * RB;
    int b   = blockIdx.y;

    const float4* c0 = (const float4*)(world + (long)b * CHWn);
    const float4* c1 = c0 + HW4n;

    // load ch1 band into smem (12 rows, own column)
#pragma unroll
    for (int ri = 0; ri < S1R; ri++)
        s1[ri][w4] = c1[((hh0 - 2 + ri) & HMASK) * W4n + w4];
    __syncthreads();

    // stage A: a1 for ri = 1..11  (a1[h] = (ch0==3) & cmp3(d, d[w-1], d[h-1], d[h-1][w-1]))
#pragma unroll
    for (int ri = 1; ri < S1R; ri++) {
        float4 e0 = c0[((hh0 - 2 + ri) & HMASK) * W4n + w4];
        float4 cC = s1[ri][w4],  cA = s1[ri - 1][w4];
        float  lC = s1[ri][w4m].w, lA = s1[ri - 1][w4m].w;
        unsigned ax = (unsigned)(e0.x == 3.0f) & cmp3(cC.x, lC,   cA.x, lA);
        unsigned ay = (unsigned)(e0.y == 3.0f) & cmp3(cC.y, cC.x, cA.y, cA.x);
        unsigned az = (unsigned)(e0.z == 3.0f) & cmp3(cC.z, cC.y, cA.z, cA.y);
        unsigned aw = (unsigned)(e0.w == 3.0f) & cmp3(cC.w, cC.z, cA.w, cA.z);
        sa1[ri - 1][w4] = ax | (ay << 8) | (az << 16) | (aw << 24);
    }
    __syncthreads();

    // stage B: d1 / e1 / a2 rolling over ri, emit code rows hh0..hh0+7
    // prologue: d1 at ri=1 (global row hh0-1)
    float4 d1vP; float d1rP;
    {
        unsigned A = sa1[0][w4], B = sa1[1][w4];
        float4 cm = s1[0][w4], cv = s1[1][w4], cp = s1[2][w4];
        d1vP.x = selv(A & 0x00000001u, B & 0x00000001u, cm.x, cv.x, cp.x);
        d1vP.y = selv(A & 0x00000100u, B & 0x00000100u, cm.y, cv.y, cp.y);
        d1vP.z = selv(A & 0x00010000u, B & 0x00010000u, cm.z, cv.z, cp.z);
        d1vP.w = selv(A & 0x01000000u, B & 0x01000000u, cm.w, cv.w, cp.w);
        unsigned Ar = sa1[0][w4p], Br = sa1[1][w4p];
        d1rP = selv(Ar & 1u, Br & 1u, s1[0][w4p].x, s1[1][w4p].x, s1[2][w4p].x);
    }
    float4 e0m = c0[((hh0 - 1) & HMASK) * W4n + w4];   // ch0 row ri=1
    float4 e0c = c0[( hh0      & HMASK) * W4n + w4];   // ch0 row ri=2
    unsigned a2P = 0;

#pragma unroll
    for (int ri = 2; ri <= RB + 2; ri++) {
        float4 e0p = c0[((hh0 - 1 + ri) & HMASK) * W4n + w4];   // ch0 row ri+1

        unsigned A = sa1[ri - 1][w4], B = sa1[ri][w4];
        float4 cm = s1[ri - 1][w4], cv = s1[ri][w4], cp = s1[ri + 1][w4];
        float4 d1v;
        d1v.x = selv(A & 0x00000001u, B & 0x00000001u, cm.x, cv.x, cp.x);
        d1v.y = selv(A & 0x00000100u, B & 0x00000100u, cm.y, cv.y, cp.y);
        d1v.z = selv(A & 0x00010000u, B & 0x00010000u, cm.z, cv.z, cp.z);
        d1v.w = selv(A & 0x01000000u, B & 0x01000000u, cm.w, cv.w, cp.w);
        unsigned Ar = sa1[ri - 1][w4p], Br = sa1[ri][w4p];
        float d1r = selv(Ar & 1u, Br & 1u,
                         s1[ri - 1][w4p].x, s1[ri][w4p].x, s1[ri + 1][w4p].x);

        // e1 = (world1 ch0 == 3) per lane
        unsigned e1x = (unsigned)(selv(A & 0x00000001u, B & 0x00000001u, e0m.x, e0c.x, e0p.x) == 3.0f);
        unsigned e1y = (unsigned)(selv(A & 0x00000100u, B & 0x00000100u, e0m.y, e0c.y, e0p.y) == 3.0f);
        unsigned e1z = (unsigned)(selv(A & 0x00010000u, B & 0x00010000u, e0m.z, e0c.z, e0p.z) == 3.0f);
        unsigned e1w = (unsigned)(selv(A & 0x01000000u, B & 0x01000000u, e0m.w, e0c.w, e0p.w) == 3.0f);

        // a2[h] = e1 & cmp3(d1, d1[w+1], d1[h-1], d1[h-1][w+1])
        unsigned a2x = e1x & cmp3(d1v.x, d1v.y, d1vP.x, d1vP.y);
        unsigned a2y = e1y & cmp3(d1v.y, d1v.z, d1vP.y, d1vP.z);
        unsigned a2z = e1z & cmp3(d1v.z, d1v.w, d1vP.z, d1vP.w);
        unsigned a2w = e1w & cmp3(d1v.w, d1r,   d1vP.w, d1rP);
        unsigned a2C = a2x | (a2y << 8) | (a2z << 16) | (a2w << 24);

        if (ri >= 3) {
            // code row h = hh0 + ri - 3: a1[h]=sa1[ri-2], a1[h+1]=sa1[ri-1]=A, a2[h]=a2P, a2[h+1]=a2C
            unsigned A0 = sa1[ri - 2][w4];
            g_code[(b << 16) + (hh0 + ri - 3) * W4n + w4] =
                A0 | (A << 1) | (a2P << 2) | (a2C << 3);
        }
        a2P = a2C; d1vP = d1v; d1rP = d1r;
        e0m = e0c; e0c = e0p;
    }
}

// ---------------- Kernel C: fused two-step apply (R14 best version, unchanged) ----------------
#define NCH 8
#define CHUNK (Hn / NCH)   // 64

__device__ __forceinline__ float4 w1vec(unsigned cw, float4 a, float4 b, float4 c) {
    float4 o;
    o.x = selv(cw & 0x00000001u, cw & 0x00000002u, a.x, b.x, c.x);
    o.y = selv(cw & 0x00000100u, cw & 0x00000200u, a.y, b.y, c.y);
    o.z = selv(cw & 0x00010000u, cw & 0x00020000u, a.z, b.z, c.z);
    o.w = selv(cw & 0x01000000u, cw & 0x02000000u, a.w, b.w, c.w);
    return o;
}
__device__ __forceinline__ float4 outvec(unsigned cw, float4 a, float4 b, float4 c) {
    float4 o;
    o.x = selv(cw & 0x00000004u, cw & 0x00000008u, a.x, b.x, c.x);
    o.y = selv(cw & 0x00000400u, cw & 0x00000800u, a.y, b.y, c.y);
    o.z = selv(cw & 0x00040000u, cw & 0x00080000u, a.z, b.z, c.z);
    o.w = selv(cw & 0x04000000u, cw & 0x08000000u, a.w, b.w, c.w);
    return o;
}

#define ROW1(L, C, QP)                                   \
    __stcs((QP), outvec(cc, t0, t1, t2));                \
    r0 = r1; r1 = r2; r2 = r3; r3 = r4; r4 = (L);        \
    t0 = t1; t1 = t2; t2 = w1vec((C), r2, r3, r4);       \
    cc = cp; cp = (C);

__global__ void __launch_bounds__(128, 8) kC(const float* __restrict__ world,
                                             float* __restrict__ out) {
    int w4 = threadIdx.x;                 // 0..127 — full row of float4
    int h0 = blockIdx.y * CHUNK;
    int bc = blockIdx.z;
    int b = bc / Cn;
    int c = bc - b * Cn;

    const float4* p = (const float4*)(world + (long)b * CHWn + (long)c * HWn) + w4;
    float4*       q = (float4*)(out + (long)b * CHWn + (long)c * HWn) + w4;
    const unsigned* ck = g_code + (b << 16) + w4;

    float4 r0 = p[((h0 - 2) & HMASK) * W4n];
    float4 r1 = p[((h0 - 1) & HMASK) * W4n];
    float4 r2 = p[h0 * W4n];
    float4 r3 = p[((h0 + 1) & HMASK) * W4n];
    float4 r4 = p[((h0 + 2) & HMASK) * W4n];

    unsigned cm = ck[((h0 - 1) & HMASK) * W4n];
    unsigned cc = ck[h0 * W4n];
    unsigned cp = ck[((h0 + 1) & HMASK) * W4n];

    float4 t0 = w1vec(cm, r0, r1, r2);
    float4 t1 = w1vec(cc, r1, r2, r3);
    float4 t2 = w1vec(cp, r2, r3, r4);

    if (blockIdx.y != NCH - 1) {
        const float4*   pl = p  + (h0 + 3) * W4n;
        const unsigned* cl = ck + (h0 + 2) * W4n;
        float4*         qs = q  + h0 * W4n;
        for (int hh = 0; hh < CHUNK; hh += 4) {
            float4 L0 = pl[0 * W4n], L1 = pl[1 * W4n], L2 = pl[2 * W4n], L3 = pl[3 * W4n];
            unsigned C0 = cl[0 * W4n], C1 = cl[1 * W4n], C2 = cl[2 * W4n], C3 = cl[3 * W4n];
            ROW1(L0, C0, qs + 0 * W4n)
            ROW1(L1, C1, qs + 1 * W4n)
            ROW1(L2, C2, qs + 2 * W4n)
            ROW1(L3, C3, qs + 3 * W4n)
            pl += 4 * W4n; cl += 4 * W4n; qs += 4 * W4n;
        }
    } else {
        for (int hh = 0; hh < CHUNK; hh += 4) {
            int h = h0 + hh;
            float4 L0 = p[((h + 3) & HMASK) * W4n];
            float4 L1 = p[((h + 4) & HMASK) * W4n];
            float4 L2 = p[((h + 5) & HMASK) * W4n];
            float4 L3 = p[((h + 6) & HMASK) * W4n];
            unsigned C0 = ck[((h + 2) & HMASK) * W4n];
            unsigned C1 = ck[((h + 3) & HMASK) * W4n];
            unsigned C2 = ck[((h + 4) & HMASK) * W4n];
            unsigned C3 = ck[((h + 5) & HMASK) * W4n];
            ROW1(L0, C0, q + (h + 0) * W4n)
            ROW1(L1, C1, q + (h + 1) * W4n)
            ROW1(L2, C2, q + (h + 2) * W4n)
            ROW1(L3, C3, q + (h + 3) * W4n)
        }
    }
}

extern "C" void kernel_launch(void* const* d_in, const int* in_sizes, int n_in,
                              void* d_out, int out_size) {
    const float* world = (const float*)d_in[0];   // (16,20,512,512) fp32
    float* out = (float*)d_out;

    dim3 mgrid(NRB, Bn);                  // (64, 16) = 1024 blocks
    kABs<<<mgrid, 128>>>(world);

    dim3 cgrid(1, NCH, Bn * Cn);          // (1, 8, 320)
    kC<<<cgrid, 128>>>(world, out);
}

// round 17
// speedup vs baseline: 1.0987x; 1.0018x over previous
#include <cuda_runtime.h>

#define Bn 16
#define Cn 20
#define Hn 512
#define Wn 512
#define W4n (Wn / 4)
#define HWn (Hn * Wn)
#define HW4n (Hn * W4n)
#define CHWn (Cn * HWn)
#define HMASK (Hn - 1)
#define W4MASK (W4n - 1)

// Scratch (__device__ globals per allocation-free rule)
__device__ unsigned g_code[Bn * HW4n];  // per byte: a1[h] | a1[h+1]<<1 | a2[h]<<2 | a2[h+1]<<3

// exact 0/1-coefficient blend, BRANCHLESS (SEL form — alu pipe)
__device__ __forceinline__ float selv(bool a, bool b, float x, float y, float z) {
    float t = b ? z : y;
    t = a ? x : t;
    return (a && b) ? (x + z) : t;
}

// (df >= d) & (da < d) & (dfa < d)
__device__ __forceinline__ unsigned cmp3(float d, float df, float da, float dfa) {
    return (unsigned)(df >= d) & (unsigned)(da < d) & (unsigned)(dfa < d);
}

// ---------------- Kernel ABs: smem-fused mask pipeline -> packed control byte ----------------
#define RB 8
#define NRB (Hn / RB)          // 64 bands
#define S1R (RB + 4)           // 12
#define SA1R (RB + 3)          // 11

__global__ void __launch_bounds__(128) kABs(const float* __restrict__ world) {
    __shared__ float4  s1[S1R][W4n];        // ch1 band rows
    __shared__ unsigned sa1[SA1R][W4n];     // a1 bits, [ri-1][w4], 0/1 per byte lane

    int w4 = threadIdx.x;                   // 0..127
    int w4m = (w4 - 1) & W4MASK;
    int w4p = (w4 + 1) & W4MASK;
    int hh0 = blockIdx.x * RB;
    int b   = blockIdx.y;

    const float4* c0 = (const float4*)(world + (long)b * CHWn);
    const float4* c1 = c0 + HW4n;

#pragma unroll
    for (int ri = 0; ri < S1R; ri++)
        s1[ri][w4] = c1[((hh0 - 2 + ri) & HMASK) * W4n + w4];
    __syncthreads();

#pragma unroll
    for (int ri = 1; ri < S1R; ri++) {
        float4 e0 = c0[((hh0 - 2 + ri) & HMASK) * W4n + w4];
        float4 cC = s1[ri][w4],  cA = s1[ri - 1][w4];
        float  lC = s1[ri][w4m].w, lA = s1[ri - 1][w4m].w;
        unsigned ax = (unsigned)(e0.x == 3.0f) & cmp3(cC.x, lC,   cA.x, lA);
        unsigned ay = (unsigned)(e0.y == 3.0f) & cmp3(cC.y, cC.x, cA.y, cA.x);
        unsigned az = (unsigned)(e0.z == 3.0f) & cmp3(cC.z, cC.y, cA.z, cA.y);
        unsigned aw = (unsigned)(e0.w == 3.0f) & cmp3(cC.w, cC.z, cA.w, cA.z);
        sa1[ri - 1][w4] = ax | (ay << 8) | (az << 16) | (aw << 24);
    }
    __syncthreads();

    float4 d1vP; float d1rP;
    {
        unsigned A = sa1[0][w4], B = sa1[1][w4];
        float4 cm = s1[0][w4], cv = s1[1][w4], cp = s1[2][w4];
        d1vP.x = selv(A & 0x00000001u, B & 0x00000001u, cm.x, cv.x, cp.x);
        d1vP.y = selv(A & 0x00000100u, B & 0x00000100u, cm.y, cv.y, cp.y);
        d1vP.z = selv(A & 0x00010000u, B & 0x00010000u, cm.z, cv.z, cp.z);
        d1vP.w = selv(A & 0x01000000u, B & 0x01000000u, cm.w, cv.w, cp.w);
        unsigned Ar = sa1[0][w4p], Br = sa1[1][w4p];
        d1rP = selv(Ar & 1u, Br & 1u, s1[0][w4p].x, s1[1][w4p].x, s1[2][w4p].x);
    }
    float4 e0m = c0[((hh0 - 1) & HMASK) * W4n + w4];
    float4 e0c = c0[( hh0      & HMASK) * W4n + w4];
    unsigned a2P = 0;

#pragma unroll
    for (int ri = 2; ri <= RB + 2; ri++) {
        float4 e0p = c0[((hh0 - 1 + ri) & HMASK) * W4n + w4];

        unsigned A = sa1[ri - 1][w4], B = sa1[ri][w4];
        float4 cm = s1[ri - 1][w4], cv = s1[ri][w4], cp = s1[ri + 1][w4];
        float4 d1v;
        d1v.x = selv(A & 0x00000001u, B & 0x00000001u, cm.x, cv.x, cp.x);
        d1v.y = selv(A & 0x00000100u, B & 0x00000100u, cm.y, cv.y, cp.y);
        d1v.z = selv(A & 0x00010000u, B & 0x00010000u, cm.z, cv.z, cp.z);
        d1v.w = selv(A & 0x01000000u, B & 0x01000000u, cm.w, cv.w, cp.w);
        unsigned Ar = sa1[ri - 1][w4p], Br = sa1[ri][w4p];
        float d1r = selv(Ar & 1u, Br & 1u,
                         s1[ri - 1][w4p].x, s1[ri][w4p].x, s1[ri + 1][w4p].x);

        unsigned e1x = (unsigned)(selv(A & 0x00000001u, B & 0x00000001u, e0m.x, e0c.x, e0p.x) == 3.0f);
        unsigned e1y = (unsigned)(selv(A & 0x00000100u, B & 0x00000100u, e0m.y, e0c.y, e0p.y) == 3.0f);
        unsigned e1z = (unsigned)(selv(A & 0x00010000u, B & 0x00010000u, e0m.z, e0c.z, e0p.z) == 3.0f);
        unsigned e1w = (unsigned)(selv(A & 0x01000000u, B & 0x01000000u, e0m.w, e0c.w, e0p.w) == 3.0f);

        unsigned a2x = e1x & cmp3(d1v.x, d1v.y, d1vP.x, d1vP.y);
        unsigned a2y = e1y & cmp3(d1v.y, d1v.z, d1vP.y, d1vP.z);
        unsigned a2z = e1z & cmp3(d1v.z, d1v.w, d1vP.z, d1vP.w);
        unsigned a2w = e1w & cmp3(d1v.w, d1r,   d1vP.w, d1rP);
        unsigned a2C = a2x | (a2y << 8) | (a2z << 16) | (a2w << 24);

        if (ri >= 3) {
            unsigned A0 = sa1[ri - 2][w4];
            g_code[(b << 16) + (hh0 + ri - 3) * W4n + w4] =
                A0 | (A << 1) | (a2P << 2) | (a2C << 3);
        }
        a2P = a2C; d1vP = d1v; d1rP = d1r;
        e0m = e0c; e0c = e0p;
    }
}

// ---------------- Kernel C: fused two-step apply, pipe-split selects ----------------
#define NCH 8
#define CHUNK (Hn / NCH)   // 64

// exact 0/1-coefficient blend on the FMA pipe (bits 0,1 of ab):
// af,bf,cf in {0.0f,1.0f} exactly; out = x*af + (z*bf + y*cf)
__device__ __forceinline__ float sel_fma(unsigned ab, float x, float y, float z) {
    float af = __uint_as_float((ab & 1u) * 0x3F800000u);   // LOP + IMAD
    float bf = __uint_as_float((ab & 2u) * 0x1FC00000u);   // LOP + IMAD (2*0x1FC00000 = 1.0f)
    float t  = 1.0f - af;                                  // FADD
    float cf = fmaf(-bf, t, t);                            // FFMA: (1-af)(1-bf)
    return fmaf(x, af, fmaf(z, bf, y * cf));               // FMUL + 2*FFMA
}

// w1 stage (bits 0,1 per byte) — FFMA form, fma pipe
__device__ __forceinline__ float4 w1vec(unsigned cw, float4 a, float4 b, float4 c) {
    float4 o;
    o.x = sel_fma(cw,       a.x, b.x, c.x);
    o.y = sel_fma(cw >> 8,  a.y, b.y, c.y);
    o.z = sel_fma(cw >> 16, a.z, b.z, c.z);
    o.w = sel_fma(cw >> 24, a.w, b.w, c.w);
    return o;
}
// out stage (bits 2,3 per byte) — SEL form, alu pipe
__device__ __forceinline__ float4 outvec(unsigned cw, float4 a, float4 b, float4 c) {
    float4 o;
    o.x = selv(cw & 0x00000004u, cw & 0x00000008u, a.x, b.x, c.x);
    o.y = selv(cw & 0x00000400u, cw & 0x00000800u, a.y, b.y, c.y);
    o.z = selv(cw & 0x00040000u, cw & 0x00080000u, a.z, b.z, c.z);
    o.w = selv(cw & 0x04000000u, cw & 0x08000000u, a.w, b.w, c.w);
    return o;
}

#define ROW1(L, C, QP)                                   \
    __stcs((QP), outvec(cc, t0, t1, t2));                \
    r0 = r1; r1 = r2; r2 = r3; r3 = r4; r4 = (L);        \
    t0 = t1; t1 = t2; t2 = w1vec((C), r2, r3, r4);       \
    cc = cp; cp = (C);

__global__ void __launch_bounds__(128, 8) kC(const float* __restrict__ world,
                                             float* __restrict__ out) {
    int w4 = threadIdx.x;                 // 0..127 — full row of float4
    int h0 = blockIdx.y * CHUNK;
    int bc = blockIdx.z;
    int b = bc / Cn;
    int c = bc - b * Cn;

    const float4* p = (const float4*)(world + (long)b * CHWn + (long)c * HWn) + w4;
    float4*       q = (float4*)(out + (long)b * CHWn + (long)c * HWn) + w4;
    const unsigned* ck = g_code + (b << 16) + w4;

    float4 r0 = p[((h0 - 2) & HMASK) * W4n];
    float4 r1 = p[((h0 - 1) & HMASK) * W4n];
    float4 r2 = p[h0 * W4n];
    float4 r3 = p[((h0 + 1) & HMASK) * W4n];
    float4 r4 = p[((h0 + 2) & HMASK) * W4n];

    unsigned cm = ck[((h0 - 1) & HMASK) * W4n];
    unsigned cc = ck[h0 * W4n];
    unsigned cp = ck[((h0 + 1) & HMASK) * W4n];

    float4 t0 = w1vec(cm, r0, r1, r2);
    float4 t1 = w1vec(cc, r1, r2, r3);
    float4 t2 = w1vec(cp, r2, r3, r4);

    if (blockIdx.y != NCH - 1) {
        const float4*   pl = p  + (h0 + 3) * W4n;
        const unsigned* cl = ck + (h0 + 2) * W4n;
        float4*         qs = q  + h0 * W4n;
        for (int hh = 0; hh < CHUNK; hh += 4) {
            float4 L0 = pl[0 * W4n], L1 = pl[1 * W4n], L2 = pl[2 * W4n], L3 = pl[3 * W4n];
            unsigned C0 = cl[0 * W4n], C1 = cl[1 * W4n], C2 = cl[2 * W4n], C3 = cl[3 * W4n];
            ROW1(L0, C0, qs + 0 * W4n)
            ROW1(L1, C1, qs + 1 * W4n)
            ROW1(L2, C2, qs + 2 * W4n)
            ROW1(L3, C3, qs + 3 * W4n)
            pl += 4 * W4n; cl += 4 * W4n; qs += 4 * W4n;
        }
    } else {
        for (int hh = 0; hh < CHUNK; hh += 4) {
            int h = h0 + hh;
            float4 L0 = p[((h + 3) & HMASK) * W4n];
            float4 L1 = p[((h + 4) & HMASK) * W4n];
            float4 L2 = p[((h + 5) & HMASK) * W4n];
            float4 L3 = p[((h + 6) & HMASK) * W4n];
            unsigned C0 = ck[((h + 2) & HMASK) * W4n];
            unsigned C1 = ck[((h + 3) & HMASK) * W4n];
            unsigned C2 = ck[((h + 4) & HMASK) * W4n];
            unsigned C3 = ck[((h + 5) & HMASK) * W4n];
            ROW1(L0, C0, q + (h + 0) * W4n)
            ROW1(L1, C1, q + (h + 1) * W4n)
            ROW1(L2, C2, q + (h + 2) * W4n)
            ROW1(L3, C3, q + (h + 3) * W4n)
        }
    }
}

extern "C" void kernel_launch(void* const* d_in, const int* in_sizes, int n_in,
                              void* d_out, int out_size) {
    const float* world = (const float*)d_in[0];   // (16,20,512,512) fp32
    float* out = (float*)d_out;

    dim3 mgrid(NRB, Bn);                  // (64, 16) = 1024 blocks
    kABs<<<mgrid, 128>>>(world);

    dim3 cgrid(1, NCH, Bn * Cn);          // (1, 8, 320)
    kC<<<cgrid, 128>>>(world, out);
}